// round 1
// baseline (speedup 1.0000x reference)
#include <cuda_runtime.h>
#include <math.h>
#include <cstdint>

// Problem constants (fixed instance: B=2, T=1024, H=1024, E=16, FF=1024, top-4)
#define S  2048
#define H  1024
#define E  16
#define FF 1024
#define TK 4
#define CLIPV 7.0f
#define AUXC 0.02f

// ---------------- scratch (static device globals; no allocations) ----------------
__device__ float g_act[(size_t)S * TK * FF];   // 32 MB  SwiGLU activations per assignment row
__device__ float g_eo [(size_t)S * TK * H];    // 32 MB  per-assignment expert outputs
__device__ int   g_topk_i[S * TK];
__device__ float g_topk_w[S * TK];
__device__ int   g_count[E];
__device__ int   g_offset[E + 1];
__device__ int   g_fill[E];
__device__ int   g_tok[S * TK];                // assignment row -> token id
__device__ int   g_rowOf[S * TK];              // (s,k) -> assignment row
__device__ float g_imp[E];                     // sum of softmax probs per expert
__device__ int   g_load[TK];                   // argmax-position histogram (faithful aux)

// ---------------- packed f32x2 FMA helpers (sm_100+) ----------------
__device__ __forceinline__ unsigned long long pack2(float a) {
    unsigned long long r;
    asm("mov.b64 %0, {%1, %1};" : "=l"(r) : "f"(a));
    return r;
}
__device__ __forceinline__ void fma2(unsigned long long& d, unsigned long long a,
                                     unsigned long long b) {
    asm("fma.rn.f32x2 %0, %1, %2, %0;" : "+l"(d) : "l"(a), "l"(b));
}
__device__ __forceinline__ float2 unpack2(unsigned long long v) {
    float2 r;
    asm("mov.b64 {%0, %1}, %2;" : "=f"(r.x), "=f"(r.y) : "l"(v));
    return r;
}

// ---------------- init ----------------
__global__ void init_kernel() {
    int t = threadIdx.x;
    if (t < E) { g_count[t] = 0; g_fill[t] = 0; g_imp[t] = 0.f; }
    if (t < TK) g_load[t] = 0;
}

// ---------------- router: logits, top-4, softmax gates, aux stats ----------------
__global__ void router_kernel(const float* __restrict__ x,
                              const float* __restrict__ rw,
                              const float* __restrict__ rb) {
    int warp = threadIdx.x >> 5, lane = threadIdx.x & 31;
    int s = blockIdx.x * 8 + warp;
    __shared__ float s_imp[E];
    __shared__ int s_cnt[E];
    __shared__ int s_load[TK];
    if (threadIdx.x < E) { s_imp[threadIdx.x] = 0.f; s_cnt[threadIdx.x] = 0; }
    if (threadIdx.x < TK) s_load[threadIdx.x] = 0;
    __syncthreads();

    const float* xr = x + (size_t)s * H;
    float xv[32];
#pragma unroll
    for (int j = 0; j < 32; j++) xv[j] = xr[j * 32 + lane];

    float logit[E];
#pragma unroll
    for (int e = 0; e < E; e++) {
        const float* w = rw + e * H;
        float acc = 0.f;
#pragma unroll
        for (int j = 0; j < 32; j++) acc += xv[j] * w[j * 32 + lane];
#pragma unroll
        for (int o = 16; o; o >>= 1) acc += __shfl_xor_sync(0xffffffffu, acc, o);
        logit[e] = acc + rb[e];
    }

    if (lane == 0) {
        // top-4 (descending value, lowest index on ties — matches lax.top_k)
        int idx[TK]; float val[TK];
        unsigned used = 0;
#pragma unroll
        for (int k = 0; k < TK; k++) {
            float best = -INFINITY; int bi = 0;
            for (int e = 0; e < E; e++)
                if (!((used >> e) & 1) && logit[e] > best) { best = logit[e]; bi = e; }
            used |= 1u << bi; idx[k] = bi; val[k] = best;
        }
        // softmax over top-4 values
        float m = val[0], z = 0.f, ex[TK];
#pragma unroll
        for (int k = 0; k < TK; k++) { ex[k] = expf(val[k] - m); z += ex[k]; }
#pragma unroll
        for (int k = 0; k < TK; k++) {
            g_topk_i[s * TK + k] = idx[k];
            g_topk_w[s * TK + k] = ex[k] / z;
            atomicAdd(&s_cnt[idx[k]], 1);
        }
        // full softmax probs -> importance
        float Z = 0.f;
        for (int e = 0; e < E; e++) Z += expf(logit[e] - val[0]);
        for (int e = 0; e < E; e++) atomicAdd(&s_imp[e], expf(logit[e] - val[0]) / Z);
        // faithful "load": argmax POSITION of the topk index vector
        int p = 0;
#pragma unroll
        for (int k = 1; k < TK; k++) if (idx[k] > idx[p]) p = k;
        atomicAdd(&s_load[p], 1);
    }
    __syncthreads();
    if (threadIdx.x < E) {
        atomicAdd(&g_imp[threadIdx.x], s_imp[threadIdx.x]);
        atomicAdd(&g_count[threadIdx.x], s_cnt[threadIdx.x]);
    }
    if (threadIdx.x < TK) atomicAdd(&g_load[threadIdx.x], s_load[threadIdx.x]);
}

// ---------------- tiny scan + aux loss ----------------
__global__ void scan_aux_kernel(float* __restrict__ out, int write_aux) {
    int off = 0;
    for (int e = 0; e < E; e++) { g_offset[e] = off; off += g_count[e]; }
    g_offset[E] = off;
    if (write_aux) {
        float aux = 0.f;
        for (int e = 0; e < TK; e++)
            aux += (g_imp[e] / (float)S) * ((float)g_load[e] / (float)S);
        out[(size_t)S * H] = AUXC * (float)E * aux;
    }
}

// ---------------- build per-expert token lists ----------------
__global__ void fill_kernel() {
    int s = blockIdx.x * blockDim.x + threadIdx.x;
    if (s >= S) return;
#pragma unroll
    for (int k = 0; k < TK; k++) {
        int e = g_topk_i[s * TK + k];
        int pos = g_offset[e] + atomicAdd(&g_fill[e], 1);
        g_tok[pos] = s;
        g_rowOf[s * TK + k] = pos;
    }
}

// ---------------- GEMM1 + SwiGLU: act[r,f] = silu(clip(gate))*clip(up) ----------------
// 64x64 tile, k-slice 16, 256 threads, each thread 4 rows x 4 cols (up+gate fused)
__global__ __launch_bounds__(256) void gemm1_kernel(const float* __restrict__ x,
                                                    const float* __restrict__ Win,
                                                    const float* __restrict__ bin) {
    int e = blockIdx.z;
    int cnt = g_count[e];
    int rowTile = blockIdx.y;
    if (rowTile * 64 >= cnt) return;
    int base = g_offset[e];
    int f0 = blockIdx.x * 64;
    int tid = threadIdx.x;
    int tx = tid & 15, ty = tid >> 4;

    __shared__ float As[64][20];   // pad 20: 16B-aligned rows, ty-broadcast conflict-free
    __shared__ float Bu[16][64];
    __shared__ float Bg[16][64];

    int lr = tid >> 2, lc = tid & 3;
    int arow = rowTile * 64 + lr;
    int tok = g_tok[base + (arow < cnt ? arow : cnt - 1)];
    const float* xrow = x + (size_t)tok * H + lc * 4;

    int bkk = tid >> 4, bc = (tid & 15) * 4;
    const float* buSrc = Win + (size_t)e * H * 2 * FF + (size_t)bkk * 2 * FF + f0 + bc;
    const float* bgSrc = buSrc + FF;

    unsigned long long accU[4][2] = {}, accG[4][2] = {};

    for (int k0 = 0; k0 < H; k0 += 16) {
        *(float4*)&As[lr][lc * 4] = *(const float4*)(xrow + k0);
        *(float4*)&Bu[bkk][bc] = *(const float4*)(buSrc + (size_t)k0 * 2 * FF);
        *(float4*)&Bg[bkk][bc] = *(const float4*)(bgSrc + (size_t)k0 * 2 * FF);
        __syncthreads();
#pragma unroll
        for (int kk = 0; kk < 16; kk++) {
            ulonglong2 bu = *(const ulonglong2*)&Bu[kk][tx * 4];
            ulonglong2 bg = *(const ulonglong2*)&Bg[kk][tx * 4];
#pragma unroll
            for (int i = 0; i < 4; i++) {
                unsigned long long a = pack2(As[ty * 4 + i][kk]);
                fma2(accU[i][0], a, bu.x); fma2(accU[i][1], a, bu.y);
                fma2(accG[i][0], a, bg.x); fma2(accG[i][1], a, bg.y);
            }
        }
        __syncthreads();
    }

    const float* biu = bin + (size_t)e * 2 * FF + f0 + tx * 4;
    const float* big = biu + FF;
#pragma unroll
    for (int i = 0; i < 4; i++) {
        int lrow = rowTile * 64 + ty * 4 + i;
        if (lrow >= cnt) continue;
        int ar = base + lrow;
        float2 u0 = unpack2(accU[i][0]), u1 = unpack2(accU[i][1]);
        float2 q0 = unpack2(accG[i][0]), q1 = unpack2(accG[i][1]);
        float up[4] = {u0.x, u0.y, u1.x, u1.y};
        float gt[4] = {q0.x, q0.y, q1.x, q1.y};
        float4 o;
        float* op = &o.x;
#pragma unroll
        for (int j = 0; j < 4; j++) {
            float u = up[j] + biu[j];
            float g = gt[j] + big[j];
            u = fminf(fmaxf(u, -CLIPV), CLIPV);
            g = fminf(fmaxf(g, -CLIPV), CLIPV);
            float sg = 1.f / (1.f + __expf(-g));
            op[j] = g * sg * u;
        }
        *(float4*)&g_act[(size_t)ar * FF + f0 + tx * 4] = o;
    }
}

// ---------------- GEMM2: eo[r,h] = act[r] @ W_out[e] + b_out[e] ----------------
__global__ __launch_bounds__(256) void gemm2_kernel(const float* __restrict__ Wout,
                                                    const float* __restrict__ bout) {
    int e = blockIdx.z;
    int cnt = g_count[e];
    int rowTile = blockIdx.y;
    if (rowTile * 64 >= cnt) return;
    int base = g_offset[e];
    int h0 = blockIdx.x * 64;
    int tid = threadIdx.x;
    int tx = tid & 15, ty = tid >> 4;

    __shared__ float As[64][20];
    __shared__ float Bs[16][64];

    int lr = tid >> 2, lc = tid & 3;
    int arow = rowTile * 64 + lr;
    const float* asrc = g_act + (size_t)(base + (arow < cnt ? arow : cnt - 1)) * FF + lc * 4;
    int bkk = tid >> 4, bc = (tid & 15) * 4;
    const float* bsrc = Wout + (size_t)e * FF * H + (size_t)bkk * H + h0 + bc;

    unsigned long long acc[4][2] = {};

    for (int k0 = 0; k0 < FF; k0 += 16) {
        *(float4*)&As[lr][lc * 4] = *(const float4*)(asrc + k0);
        *(float4*)&Bs[bkk][bc] = *(const float4*)(bsrc + (size_t)k0 * H);
        __syncthreads();
#pragma unroll
        for (int kk = 0; kk < 16; kk++) {
            ulonglong2 b = *(const ulonglong2*)&Bs[kk][tx * 4];
#pragma unroll
            for (int i = 0; i < 4; i++) {
                unsigned long long a = pack2(As[ty * 4 + i][kk]);
                fma2(acc[i][0], a, b.x); fma2(acc[i][1], a, b.y);
            }
        }
        __syncthreads();
    }

    const float* bo = bout + (size_t)e * H + h0 + tx * 4;
#pragma unroll
    for (int i = 0; i < 4; i++) {
        int lrow = rowTile * 64 + ty * 4 + i;
        if (lrow >= cnt) continue;
        int ar = base + lrow;
        float2 a0 = unpack2(acc[i][0]), a1 = unpack2(acc[i][1]);
        float4 o = {a0.x + bo[0], a0.y + bo[1], a1.x + bo[2], a1.y + bo[3]};
        *(float4*)&g_eo[(size_t)ar * H + h0 + tx * 4] = o;
    }
}

// ---------------- combine: out[s] = sum_k w_k * eo[row(s,k)] ----------------
__global__ void combine_kernel(float* __restrict__ out) {
    int s = blockIdx.x;
    __shared__ float w[TK];
    __shared__ int rr[TK];
    if (threadIdx.x < TK) {
        w[threadIdx.x] = g_topk_w[s * TK + threadIdx.x];
        rr[threadIdx.x] = g_rowOf[s * TK + threadIdx.x];
    }
    __syncthreads();
    int h = threadIdx.x * 4;
    float4 a = {0.f, 0.f, 0.f, 0.f};
#pragma unroll
    for (int k = 0; k < TK; k++) {
        float4 v = *(const float4*)&g_eo[(size_t)rr[k] * H + h];
        a.x += w[k] * v.x; a.y += w[k] * v.y; a.z += w[k] * v.z; a.w += w[k] * v.w;
    }
    *(float4*)&out[(size_t)s * H + h] = a;
}

// ---------------- launch ----------------
extern "C" void kernel_launch(void* const* d_in, const int* in_sizes, int n_in,
                              void* d_out, int out_size) {
    const float* x    = (const float*)d_in[0];
    const float* Win  = (const float*)d_in[1];
    const float* bin  = (const float*)d_in[2];
    const float* Wout = (const float*)d_in[3];
    const float* bout = (const float*)d_in[4];
    const float* rw   = (const float*)d_in[5];
    const float* rb   = (const float*)d_in[6];
    float* out = (float*)d_out;

    int write_aux = (out_size > S * H) ? 1 : 0;

    init_kernel<<<1, 32>>>();
    router_kernel<<<S / 8, 256>>>(x, rw, rb);
    scan_aux_kernel<<<1, 1>>>(out, write_aux);
    fill_kernel<<<S / 256, 256>>>();
    gemm1_kernel<<<dim3(FF / 64, S / 64, E), 256>>>(x, Win, bin);
    gemm2_kernel<<<dim3(H / 64, S / 64, E), 256>>>(Wout, bout);
    combine_kernel<<<S, 256>>>(out);
}